// round 13
// baseline (speedup 1.0000x reference)
#include <cuda_runtime.h>

#define T_LEN   16384
#define NUMB    64
#define KTAPS   129
#define TILE_T  128
#define BPB     8       // bands per block (1 per warp)
#define THREADS 256
#define NGROUPS (NUMB / BPB)
#define NTILES  (T_LEN / TILE_T)

// t-major partials: 8 floats (=2x float4) per t, one slot per band group
__device__ float4 g_part[T_LEN][2];
// per-tile arrival tickets; zero-init at load, reset by finalizer each launch
__device__ int g_cnt[NTILES];

__device__ __forceinline__ float ex2f(float x) {
    float r; asm("ex2.approx.ftz.f32 %0, %1;" : "=f"(r) : "f"(x)); return r;
}
__device__ __forceinline__ float sqrtaf(float x) {
    float r; asm("sqrt.approx.f32 %0, %1;" : "=f"(r) : "f"(x)); return r;
}

__global__ __launch_bounds__(THREADS, 4)
void fused_kernel(const float* __restrict__ xr, const float* __restrict__ xi,
                  const float* __restrict__ w1r, const float* __restrict__ w1i,
                  const float* __restrict__ cr,  const float* __restrict__ ci,
                  const float* __restrict__ sr,  const float* __restrict__ si,
                  const float* __restrict__ fr,  const float* __restrict__ fi,
                  const float* __restrict__ w3r, const float* __restrict__ w3i,
                  float* __restrict__ out)
{
    // conv x-arrays and sred never live simultaneously -> union (sync-guarded)
    __shared__ __align__(16) union {
        struct { float r[TILE_T + 128]; float i[TILE_T + 128]; float s[TILE_T + 128]; } cx;
        float sred[BPB][TILE_T];
    } u;
    __shared__ __align__(16) float swr[BPB][132];   // wr
    __shared__ __align__(16) float swd[BPB][132];   // wi - wr
    __shared__ __align__(16) float sws[BPB][132];   // wi + wr
    __shared__ __align__(16) float4 sPq[BPB][NUMB]; // {pxr, pyr, pxi, pyi}
    __shared__ __align__(16) float2 sPw[BPB][NUMB]; // {fc_r*2^pzr, fc_i*2^pzi}
    __shared__ int s_ticket;

    const int tid  = threadIdx.x;
    const int wb   = tid >> 5;        // local band (warp)
    const int lane = tid & 31;
    const int tile = blockIdx.x;
    const int tileBase = tile * TILE_T;
    const int band = blockIdx.y * BPB + wb;

    // ---- stage x tile + halo (r, i, and s = r+i) ----
    for (int i = tid; i < TILE_T + 128; i += THREADS) {
        int t = tileBase - 64 + i;
        bool ok = (t >= 0) && (t < T_LEN);
        float vr = ok ? xr[t] : 0.0f;
        float vi = ok ? xi[t] : 0.0f;
        u.cx.r[i] = vr;
        u.cx.i[i] = vi;
        u.cx.s[i] = vr + vi;
    }
    // ---- stage Karatsuba weight triplets ----
    for (int i = tid; i < BPB * KTAPS; i += THREADS) {
        int bb = i / KTAPS, k = i - bb * KTAPS;
        int gb = blockIdx.y * BPB + bb;
        float wr = w1r[gb * KTAPS + k];
        float wi = w1i[gb * KTAPS + k];
        swr[bb][k] = wr;
        swd[bb][k] = wi - wr;
        sws[bb][k] = wi + wr;
    }
    // ---- inline RBF param precompute (2^pz folded into mixture weight) ----
    const float L = 1.4426950408889634f;  // log2(e)
    for (int i = tid; i < BPB * NUMB; i += THREADS) {
        int bb = i >> 6, c = i & 63;
        int idx = (blockIdx.y * BPB + bb) * NUMB + c;
        float s  = __ldg(&sr[idx]) * L;
        float cc = __ldg(&cr[idx]);
        float pxr = -s, pyr = 2.0f * s * cc;
        float pwr = __ldg(&fr[idx]) * ex2f(-s * cc * cc);
        s  = __ldg(&si[idx]) * L;
        cc = __ldg(&ci[idx]);
        float pxi = -s, pyi = 2.0f * s * cc;
        float pwi = __ldg(&fi[idx]) * ex2f(-s * cc * cc);
        sPq[bb][c] = make_float4(pxr, pyr, pxi, pyi);
        sPw[bb][c] = make_float2(pwr, pwi);
    }
    __syncthreads();

    const float4* xs4 = (const float4*)u.cx.s;
    const float4* xr4 = (const float4*)u.cx.r;
    const float4* xi4 = (const float4*)u.cx.i;

    // ============================================================
    // PHASE A: Karatsuba conv for j = 0,1 (uses window elems 0..4)
    // ============================================================
    float A01[2] = {0.f,0.f}, B01[2] = {0.f,0.f}, C01[2] = {0.f,0.f};
    {
        float4 As = xs4[lane], Ar = xr4[lane], Ai = xi4[lane];
        #pragma unroll
        for (int kg = 0; kg < 32; kg++) {
            float4 Bs = xs4[lane + kg + 1];
            float4 Br = xr4[lane + kg + 1];
            float4 Bi = xi4[lane + kg + 1];
            float4 wr4 = *(const float4*)&swr[wb][4 * kg];
            float4 wd4 = *(const float4*)&swd[wb][4 * kg];
            float4 ws4 = *(const float4*)&sws[wb][4 * kg];
            float axs[5] = {As.x, As.y, As.z, As.w, Bs.x};
            float axr[5] = {Ar.x, Ar.y, Ar.z, Ar.w, Br.x};
            float axi[5] = {Ai.x, Ai.y, Ai.z, Ai.w, Bi.x};
            float wrv[4] = {wr4.x, wr4.y, wr4.z, wr4.w};
            float wdv[4] = {wd4.x, wd4.y, wd4.z, wd4.w};
            float wsv[4] = {ws4.x, ws4.y, ws4.z, ws4.w};
            #pragma unroll
            for (int kk = 0; kk < 4; kk++) {
                #pragma unroll
                for (int j = 0; j < 2; j++) {
                    A01[j] = fmaf(axs[kk + j], wrv[kk], A01[j]);
                    B01[j] = fmaf(axr[kk + j], wdv[kk], B01[j]);
                    C01[j] = fmaf(axi[kk + j], wsv[kk], C01[j]);
                }
            }
            As = Bs; Ar = Br; Ai = Bi;
        }
        // tail tap k = 128 (window at lane+32 already in As/Ar/Ai)
        float wr = swr[wb][128], wd = swd[wb][128], ws = sws[wb][128];
        float ts[2] = {As.x, As.y};
        float tr[2] = {Ar.x, Ar.y};
        float ti[2] = {Ai.x, Ai.y};
        #pragma unroll
        for (int j = 0; j < 2; j++) {
            A01[j] = fmaf(ts[j], wr, A01[j]);
            B01[j] = fmaf(tr[j], wd, B01[j]);
            C01[j] = fmaf(ti[j], ws, C01[j]);
        }
    }
    float x1r01[2], x1i01[2], m01[2], a01[2];
    #pragma unroll
    for (int j = 0; j < 2; j++) {
        x1r01[j] = A01[j] - C01[j];
        x1i01[j] = A01[j] + B01[j];
        m01[j] = x1r01[j] * x1r01[j] + x1i01[j] * x1i01[j];
        a01[j] = sqrtaf(m01[j]);
    }

    // =====================================================================
    // PHASE B (fused): conv j=2,3 step + 2 RBF centers for j01 per kg-iter
    // conv j23 uses window elems kk+2..kk+3+3 (indices 2..7)
    // =====================================================================
    float A23[2] = {0.f,0.f}, B23[2] = {0.f,0.f}, C23[2] = {0.f,0.f};
    float oR01[2] = {0.f,0.f}, oI01[2] = {0.f,0.f};
    {
        float4 As = xs4[lane], Ar = xr4[lane], Ai = xi4[lane];
        #pragma unroll
        for (int kg = 0; kg < 32; kg++) {
            float4 Bs = xs4[lane + kg + 1];
            float4 Br = xr4[lane + kg + 1];
            float4 Bi = xi4[lane + kg + 1];
            float4 wr4 = *(const float4*)&swr[wb][4 * kg];
            float4 wd4 = *(const float4*)&swd[wb][4 * kg];
            float4 ws4 = *(const float4*)&sws[wb][4 * kg];
            float axs[8] = {As.x, As.y, As.z, As.w, Bs.x, Bs.y, Bs.z, Bs.w};
            float axr[8] = {Ar.x, Ar.y, Ar.z, Ar.w, Br.x, Br.y, Br.z, Br.w};
            float axi[8] = {Ai.x, Ai.y, Ai.z, Ai.w, Bi.x, Bi.y, Bi.z, Bi.w};
            float wrv[4] = {wr4.x, wr4.y, wr4.z, wr4.w};
            float wdv[4] = {wd4.x, wd4.y, wd4.z, wd4.w};
            float wsv[4] = {ws4.x, ws4.y, ws4.z, ws4.w};
            #pragma unroll
            for (int kk = 0; kk < 4; kk++) {
                #pragma unroll
                for (int j = 0; j < 2; j++) {
                    A23[j] = fmaf(axs[kk + j + 2], wrv[kk], A23[j]);
                    B23[j] = fmaf(axr[kk + j + 2], wdv[kk], B23[j]);
                    C23[j] = fmaf(axi[kk + j + 2], wsv[kk], C23[j]);
                }
            }
            // 2 RBF centers for j01 (XU work overlapped with conv FMA)
            #pragma unroll
            for (int dc = 0; dc < 2; dc++) {
                int c = 2 * kg + dc;
                float4 q = sPq[wb][c];
                float2 w = sPw[wb][c];
                #pragma unroll
                for (int j = 0; j < 2; j++) {
                    float er = ex2f(fmaf(m01[j], q.x, a01[j] * q.y));
                    oR01[j] = fmaf(er, w.x, oR01[j]);
                    float ei = ex2f(fmaf(m01[j], q.z, a01[j] * q.w));
                    oI01[j] = fmaf(ei, w.y, oI01[j]);
                }
            }
            As = Bs; Ar = Br; Ai = Bi;
        }
        // tail tap k = 128 for j23
        float wr = swr[wb][128], wd = swd[wb][128], ws = sws[wb][128];
        float ts[2] = {As.z, As.w};
        float tr[2] = {Ar.z, Ar.w};
        float ti[2] = {Ai.z, Ai.w};
        #pragma unroll
        for (int j = 0; j < 2; j++) {
            A23[j] = fmaf(ts[j], wr, A23[j]);
            B23[j] = fmaf(tr[j], wd, B23[j]);
            C23[j] = fmaf(ti[j], ws, C23[j]);
        }
    }
    float x1r23[2], x1i23[2], m23[2], a23[2];
    #pragma unroll
    for (int j = 0; j < 2; j++) {
        x1r23[j] = A23[j] - C23[j];
        x1i23[j] = A23[j] + B23[j];
        m23[j] = x1r23[j] * x1r23[j] + x1i23[j] * x1i23[j];
        a23[j] = sqrtaf(m23[j]);
    }

    // ============================================================
    // PHASE C: RBF for j = 2,3
    // ============================================================
    float oR23[2] = {0.f,0.f}, oI23[2] = {0.f,0.f};
    #pragma unroll 4
    for (int c = 0; c < NUMB; c++) {
        float4 q = sPq[wb][c];
        float2 w = sPw[wb][c];
        #pragma unroll
        for (int j = 0; j < 2; j++) {
            float er = ex2f(fmaf(m23[j], q.x, a23[j] * q.y));
            oR23[j] = fmaf(er, w.x, oR23[j]);
            float ei = ex2f(fmaf(m23[j], q.z, a23[j] * q.w));
            oI23[j] = fmaf(ei, w.y, oI23[j]);
        }
    }

    // ---- combine + band weight (real output only) ----
    float w3rb = __ldg(&w3r[band]);
    float w3ib = __ldg(&w3i[band]);
    float yv[4];
    #pragma unroll
    for (int j = 0; j < 2; j++) {
        float q   = oR01[j] + 1.0f;
        float x2r = q * x1r01[j] - oI01[j] * x1i01[j];
        float x2i = q * x1i01[j] + oI01[j] * x1r01[j];
        yv[j] = x2r * w3rb - x2i * w3ib;
        q   = oR23[j] + 1.0f;
        x2r = q * x1r23[j] - oI23[j] * x1i23[j];
        x2i = q * x1i23[j] + oI23[j] * x1r23[j];
        yv[j + 2] = x2r * w3rb - x2i * w3ib;
    }
    __syncthreads();   // all warps done reading u.cx before overlay reuse
    #pragma unroll
    for (int j = 0; j < 4; j++)
        u.sred[wb][4 * lane + j] = yv[j];
    __syncthreads();

    // ---- reduce 8 bands within block; publish t-major partial ----
    if (tid < TILE_T) {
        float r = 0.f;
        #pragma unroll
        for (int w = 0; w < BPB; w++) r += u.sred[w][tid];
        ((float*)&g_part[tileBase + tid][0])[blockIdx.y] = r;
    }

    // ---- fence + ticket: last block of this tile finalizes ----
    __threadfence();
    if (tid == 0)
        s_ticket = atomicAdd(&g_cnt[tile], 1);
    __syncthreads();
    if (s_ticket == NGROUPS - 1) {
        if (tid < TILE_T) {
            int t = tileBase + tid;
            float4 pa = g_part[t][0];
            float4 pb = g_part[t][1];
            out[t] = ((pa.x + pa.y) + (pa.z + pa.w)) + ((pb.x + pb.y) + (pb.z + pb.w));
        }
        if (tid == 0)
            g_cnt[tile] = 0;   // reset for next launch / graph replay
    }
}

extern "C" void kernel_launch(void* const* d_in, const int* in_sizes, int n_in,
                              void* d_out, int out_size)
{
    // Input ordering: order A (dict/signature) confirmed (in_sizes[0]==16384).
    int I_xr, I_xi, I_w1r, I_w1i, I_cr, I_ci, I_sr, I_si, I_fcr, I_fci, I_w3r, I_w3i;
    if (in_sizes[0] == T_LEN) {
        I_xr = 0;  I_xi = 1;  I_w1r = 2; I_w1i = 3; I_cr = 4;  I_ci = 5;
        I_sr = 6;  I_si = 7;  I_fcr = 8; I_fci = 9; I_w3r = 10; I_w3i = 11;
    } else {
        I_ci = 0;  I_cr = 1;  I_fci = 2; I_fcr = 3; I_si = 4;  I_sr = 5;
        I_w1i = 6; I_w1r = 7; I_w3i = 8; I_w3r = 9; I_xi = 10; I_xr = 11;
    }

    const float* x_r  = (const float*)d_in[I_xr];
    const float* x_i  = (const float*)d_in[I_xi];
    const float* w1_r = (const float*)d_in[I_w1r];
    const float* w1_i = (const float*)d_in[I_w1i];
    const float* c_r  = (const float*)d_in[I_cr];
    const float* c_i  = (const float*)d_in[I_ci];
    const float* s_r  = (const float*)d_in[I_sr];
    const float* s_i  = (const float*)d_in[I_si];
    const float* fc_r = (const float*)d_in[I_fcr];
    const float* fc_i = (const float*)d_in[I_fci];
    const float* w3_r = (const float*)d_in[I_w3r];
    const float* w3_i = (const float*)d_in[I_w3i];
    float* out = (float*)d_out;

    dim3 grid(NTILES, NGROUPS);
    fused_kernel<<<grid, THREADS>>>(x_r, x_i, w1_r, w1_i,
                                    c_r, c_i, s_r, s_i, fc_r, fc_i,
                                    w3_r, w3_i, out);
}

// round 14
// speedup vs baseline: 1.1278x; 1.1278x over previous
#include <cuda_runtime.h>

#define T_LEN   16384
#define NUMB    64
#define KTAPS   129
#define TILE_T  128
#define BPB     8       // bands per block (1 per warp)
#define THREADS 256
#define NGROUPS (NUMB / BPB)
#define NTILES  (T_LEN / TILE_T)

// t-major partials: 8 floats (=2x float4) per t, one slot per band group
__device__ float4 g_part[T_LEN][2];
// per-tile arrival tickets; zero-init at load, reset by finalizer each launch
__device__ int g_cnt[NTILES];

__device__ __forceinline__ float ex2f(float x) {
    float r; asm("ex2.approx.ftz.f32 %0, %1;" : "=f"(r) : "f"(x)); return r;
}
__device__ __forceinline__ float sqrtaf(float x) {
    float r; asm("sqrt.approx.f32 %0, %1;" : "=f"(r) : "f"(x)); return r;
}

__global__ __launch_bounds__(THREADS, 3)
void fused_kernel(const float* __restrict__ xr, const float* __restrict__ xi,
                  const float* __restrict__ w1r, const float* __restrict__ w1i,
                  const float* __restrict__ cr,  const float* __restrict__ ci,
                  const float* __restrict__ sr,  const float* __restrict__ si,
                  const float* __restrict__ fr,  const float* __restrict__ fi,
                  const float* __restrict__ w3r, const float* __restrict__ w3i,
                  float* __restrict__ out)
{
    // conv x-arrays and sred never live simultaneously -> union (sync-guarded)
    __shared__ __align__(16) union {
        struct { float r[TILE_T + 128]; float i[TILE_T + 128]; float s[TILE_T + 128]; } cx;
        float sred[BPB][TILE_T];
    } u;
    __shared__ __align__(16) float swr[BPB][132];   // wr
    __shared__ __align__(16) float swd[BPB][132];   // wi - wr
    __shared__ __align__(16) float sws[BPB][132];   // wi + wr
    __shared__ __align__(16) float4 sPq[BPB][NUMB]; // {pxr, pyr, pxi, pyi}
    __shared__ __align__(16) float2 sPw[BPB][NUMB]; // {fc_r*2^pzr, fc_i*2^pzi}
    __shared__ int s_ticket;

    const int tid  = threadIdx.x;
    const int wb   = tid >> 5;        // local band (warp)
    const int lane = tid & 31;
    const int tile = blockIdx.x;
    const int tileBase = tile * TILE_T;
    const int band = blockIdx.y * BPB + wb;

    // ---- stage x tile + halo (r, i, and s = r+i) ----
    for (int i = tid; i < TILE_T + 128; i += THREADS) {
        int t = tileBase - 64 + i;
        bool ok = (t >= 0) && (t < T_LEN);
        float vr = ok ? xr[t] : 0.0f;
        float vi = ok ? xi[t] : 0.0f;
        u.cx.r[i] = vr;
        u.cx.i[i] = vi;
        u.cx.s[i] = vr + vi;
    }
    // ---- stage Karatsuba weight triplets ----
    for (int i = tid; i < BPB * KTAPS; i += THREADS) {
        int bb = i / KTAPS, k = i - bb * KTAPS;
        int gb = blockIdx.y * BPB + bb;
        float wr = w1r[gb * KTAPS + k];
        float wi = w1i[gb * KTAPS + k];
        swr[bb][k] = wr;
        swd[bb][k] = wi - wr;
        sws[bb][k] = wi + wr;
    }
    // ---- inline RBF param precompute (2^pz folded into mixture weight) ----
    const float L = 1.4426950408889634f;  // log2(e)
    for (int i = tid; i < BPB * NUMB; i += THREADS) {
        int bb = i >> 6, c = i & 63;
        int idx = (blockIdx.y * BPB + bb) * NUMB + c;
        float s  = __ldg(&sr[idx]) * L;
        float cc = __ldg(&cr[idx]);
        float pxr = -s, pyr = 2.0f * s * cc;
        float pwr = __ldg(&fr[idx]) * ex2f(-s * cc * cc);
        s  = __ldg(&si[idx]) * L;
        cc = __ldg(&ci[idx]);
        float pxi = -s, pyi = 2.0f * s * cc;
        float pwi = __ldg(&fi[idx]) * ex2f(-s * cc * cc);
        sPq[bb][c] = make_float4(pxr, pyr, pxi, pyi);
        sPw[bb][c] = make_float2(pwr, pwi);
    }
    __syncthreads();

    const float4* xs4 = (const float4*)u.cx.s;
    const float4* xr4 = (const float4*)u.cx.r;
    const float4* xi4 = (const float4*)u.cx.i;

    // ============================================================
    // PHASE A: Karatsuba conv for j = 0,1 (window elems 0..4)
    // ============================================================
    float A01[2] = {0.f,0.f}, B01[2] = {0.f,0.f}, C01[2] = {0.f,0.f};
    {
        float4 As = xs4[lane], Ar = xr4[lane], Ai = xi4[lane];
        #pragma unroll
        for (int kg = 0; kg < 32; kg++) {
            float4 Bs = xs4[lane + kg + 1];
            float4 Br = xr4[lane + kg + 1];
            float4 Bi = xi4[lane + kg + 1];
            float4 wr4 = *(const float4*)&swr[wb][4 * kg];
            float4 wd4 = *(const float4*)&swd[wb][4 * kg];
            float4 ws4 = *(const float4*)&sws[wb][4 * kg];
            float axs[5] = {As.x, As.y, As.z, As.w, Bs.x};
            float axr[5] = {Ar.x, Ar.y, Ar.z, Ar.w, Br.x};
            float axi[5] = {Ai.x, Ai.y, Ai.z, Ai.w, Bi.x};
            float wrv[4] = {wr4.x, wr4.y, wr4.z, wr4.w};
            float wdv[4] = {wd4.x, wd4.y, wd4.z, wd4.w};
            float wsv[4] = {ws4.x, ws4.y, ws4.z, ws4.w};
            #pragma unroll
            for (int kk = 0; kk < 4; kk++) {
                #pragma unroll
                for (int j = 0; j < 2; j++) {
                    A01[j] = fmaf(axs[kk + j], wrv[kk], A01[j]);
                    B01[j] = fmaf(axr[kk + j], wdv[kk], B01[j]);
                    C01[j] = fmaf(axi[kk + j], wsv[kk], C01[j]);
                }
            }
            As = Bs; Ar = Br; Ai = Bi;
        }
        // tail tap k = 128: x[4lane+j+128] = xs4[lane+32].{x,y} = carry
        float wr = swr[wb][128], wd = swd[wb][128], ws = sws[wb][128];
        float ts[2] = {As.x, As.y};
        float tr[2] = {Ar.x, Ar.y};
        float ti[2] = {Ai.x, Ai.y};
        #pragma unroll
        for (int j = 0; j < 2; j++) {
            A01[j] = fmaf(ts[j], wr, A01[j]);
            B01[j] = fmaf(tr[j], wd, B01[j]);
            C01[j] = fmaf(ti[j], ws, C01[j]);
        }
    }
    float x1r01[2], x1i01[2], m01[2], a01[2];
    #pragma unroll
    for (int j = 0; j < 2; j++) {
        x1r01[j] = A01[j] - C01[j];
        x1i01[j] = A01[j] + B01[j];
        m01[j] = x1r01[j] * x1r01[j] + x1i01[j] * x1i01[j];
        a01[j] = sqrtaf(m01[j]);
    }

    // =====================================================================
    // PHASE B (fused): conv j=2,3 (window elems 2..7, float2 carry) +
    //                  2 RBF centers for j01 per kg-iter (XU overlap)
    // =====================================================================
    float A23[2] = {0.f,0.f}, B23[2] = {0.f,0.f}, C23[2] = {0.f,0.f};
    float oR01[2] = {0.f,0.f}, oI01[2] = {0.f,0.f};
    {
        float4 t0 = xs4[lane];  float2 Ps = make_float2(t0.z, t0.w);
        float4 t1 = xr4[lane];  float2 Pr = make_float2(t1.z, t1.w);
        float4 t2 = xi4[lane];  float2 Pi = make_float2(t2.z, t2.w);
        #pragma unroll
        for (int kg = 0; kg < 32; kg++) {
            float4 Bs = xs4[lane + kg + 1];
            float4 Br = xr4[lane + kg + 1];
            float4 Bi = xi4[lane + kg + 1];
            float4 wr4 = *(const float4*)&swr[wb][4 * kg];
            float4 wd4 = *(const float4*)&swd[wb][4 * kg];
            float4 ws4 = *(const float4*)&sws[wb][4 * kg];
            // window elems 2..7 relative to base 4(lane+kg)
            float axs[6] = {Ps.x, Ps.y, Bs.x, Bs.y, Bs.z, Bs.w};
            float axr[6] = {Pr.x, Pr.y, Br.x, Br.y, Br.z, Br.w};
            float axi[6] = {Pi.x, Pi.y, Bi.x, Bi.y, Bi.z, Bi.w};
            float wrv[4] = {wr4.x, wr4.y, wr4.z, wr4.w};
            float wdv[4] = {wd4.x, wd4.y, wd4.z, wd4.w};
            float wsv[4] = {ws4.x, ws4.y, ws4.z, ws4.w};
            #pragma unroll
            for (int kk = 0; kk < 4; kk++) {
                #pragma unroll
                for (int j = 0; j < 2; j++) {
                    A23[j] = fmaf(axs[kk + j], wrv[kk], A23[j]);
                    B23[j] = fmaf(axr[kk + j], wdv[kk], B23[j]);
                    C23[j] = fmaf(axi[kk + j], wsv[kk], C23[j]);
                }
            }
            // 2 RBF centers for j01 (XU work overlapped with conv FMA)
            #pragma unroll
            for (int dc = 0; dc < 2; dc++) {
                int c = 2 * kg + dc;
                float4 q = sPq[wb][c];
                float2 w = sPw[wb][c];
                #pragma unroll
                for (int j = 0; j < 2; j++) {
                    float er = ex2f(fmaf(m01[j], q.x, a01[j] * q.y));
                    oR01[j] = fmaf(er, w.x, oR01[j]);
                    float ei = ex2f(fmaf(m01[j], q.z, a01[j] * q.w));
                    oI01[j] = fmaf(ei, w.y, oI01[j]);
                }
            }
            Ps = make_float2(Bs.z, Bs.w);
            Pr = make_float2(Br.z, Br.w);
            Pi = make_float2(Bi.z, Bi.w);
        }
        // tail tap k=128: x[4lane+2+j+128] = xs4[lane+32].{z,w} = carry
        float wr = swr[wb][128], wd = swd[wb][128], ws = sws[wb][128];
        float ts[2] = {Ps.x, Ps.y};
        float tr[2] = {Pr.x, Pr.y};
        float ti[2] = {Pi.x, Pi.y};
        #pragma unroll
        for (int j = 0; j < 2; j++) {
            A23[j] = fmaf(ts[j], wr, A23[j]);
            B23[j] = fmaf(tr[j], wd, B23[j]);
            C23[j] = fmaf(ti[j], ws, C23[j]);
        }
    }
    float x1r23[2], x1i23[2], m23[2], a23[2];
    #pragma unroll
    for (int j = 0; j < 2; j++) {
        x1r23[j] = A23[j] - C23[j];
        x1i23[j] = A23[j] + B23[j];
        m23[j] = x1r23[j] * x1r23[j] + x1i23[j] * x1i23[j];
        a23[j] = sqrtaf(m23[j]);
    }

    // ============================================================
    // PHASE C: RBF for j = 2,3
    // ============================================================
    float oR23[2] = {0.f,0.f}, oI23[2] = {0.f,0.f};
    #pragma unroll 4
    for (int c = 0; c < NUMB; c++) {
        float4 q = sPq[wb][c];
        float2 w = sPw[wb][c];
        #pragma unroll
        for (int j = 0; j < 2; j++) {
            float er = ex2f(fmaf(m23[j], q.x, a23[j] * q.y));
            oR23[j] = fmaf(er, w.x, oR23[j]);
            float ei = ex2f(fmaf(m23[j], q.z, a23[j] * q.w));
            oI23[j] = fmaf(ei, w.y, oI23[j]);
        }
    }

    // ---- combine + band weight (real output only) ----
    float w3rb = __ldg(&w3r[band]);
    float w3ib = __ldg(&w3i[band]);
    float yv[4];
    #pragma unroll
    for (int j = 0; j < 2; j++) {
        float q   = oR01[j] + 1.0f;
        float x2r = q * x1r01[j] - oI01[j] * x1i01[j];
        float x2i = q * x1i01[j] + oI01[j] * x1r01[j];
        yv[j] = x2r * w3rb - x2i * w3ib;
        q   = oR23[j] + 1.0f;
        x2r = q * x1r23[j] - oI23[j] * x1i23[j];
        x2i = q * x1i23[j] + oI23[j] * x1r23[j];
        yv[j + 2] = x2r * w3rb - x2i * w3ib;
    }
    __syncthreads();   // all warps done reading u.cx before overlay reuse
    #pragma unroll
    for (int j = 0; j < 4; j++)
        u.sred[wb][4 * lane + j] = yv[j];
    __syncthreads();

    // ---- reduce 8 bands within block; publish t-major partial ----
    if (tid < TILE_T) {
        float r = 0.f;
        #pragma unroll
        for (int w = 0; w < BPB; w++) r += u.sred[w][tid];
        ((float*)&g_part[tileBase + tid][0])[blockIdx.y] = r;
    }

    // ---- fence + ticket: last block of this tile finalizes ----
    __threadfence();
    if (tid == 0)
        s_ticket = atomicAdd(&g_cnt[tile], 1);
    __syncthreads();
    if (s_ticket == NGROUPS - 1) {
        if (tid < TILE_T) {
            int t = tileBase + tid;
            float4 pa = g_part[t][0];
            float4 pb = g_part[t][1];
            out[t] = ((pa.x + pa.y) + (pa.z + pa.w)) + ((pb.x + pb.y) + (pb.z + pb.w));
        }
        if (tid == 0)
            g_cnt[tile] = 0;   // reset for next launch / graph replay
    }
}

extern "C" void kernel_launch(void* const* d_in, const int* in_sizes, int n_in,
                              void* d_out, int out_size)
{
    // Input ordering: order A (dict/signature) confirmed (in_sizes[0]==16384).
    int I_xr, I_xi, I_w1r, I_w1i, I_cr, I_ci, I_sr, I_si, I_fcr, I_fci, I_w3r, I_w3i;
    if (in_sizes[0] == T_LEN) {
        I_xr = 0;  I_xi = 1;  I_w1r = 2; I_w1i = 3; I_cr = 4;  I_ci = 5;
        I_sr = 6;  I_si = 7;  I_fcr = 8; I_fci = 9; I_w3r = 10; I_w3i = 11;
    } else {
        I_ci = 0;  I_cr = 1;  I_fci = 2; I_fcr = 3; I_si = 4;  I_sr = 5;
        I_w1i = 6; I_w1r = 7; I_w3i = 8; I_w3r = 9; I_xi = 10; I_xr = 11;
    }

    const float* x_r  = (const float*)d_in[I_xr];
    const float* x_i  = (const float*)d_in[I_xi];
    const float* w1_r = (const float*)d_in[I_w1r];
    const float* w1_i = (const float*)d_in[I_w1i];
    const float* c_r  = (const float*)d_in[I_cr];
    const float* c_i  = (const float*)d_in[I_ci];
    const float* s_r  = (const float*)d_in[I_sr];
    const float* s_i  = (const float*)d_in[I_si];
    const float* fc_r = (const float*)d_in[I_fcr];
    const float* fc_i = (const float*)d_in[I_fci];
    const float* w3_r = (const float*)d_in[I_w3r];
    const float* w3_i = (const float*)d_in[I_w3i];
    float* out = (float*)d_out;

    dim3 grid(NTILES, NGROUPS);
    fused_kernel<<<grid, THREADS>>>(x_r, x_i, w1_r, w1_i,
                                    c_r, c_i, s_r, s_i, fc_r, fc_i,
                                    w3_r, w3_i, out);
}